// round 13
// baseline (speedup 1.0000x reference)
#include <cuda_runtime.h>
#include <cuda_bf16.h>
#include <math.h>

#define BN 4096
#define DN 256
#define HN 768

// ---------------- device scratch (static, allocation-free) ----------------
__device__ float g_G[2][256];      // single-counted 16x16 Ksum histograms (atomic, zeroed in prep)
__device__ float g_M[2][65536];    // HSIC cross products (RED-accumulated, zeroed in prep)
__device__ float g_colsum[4][256]; // column sums of normalized bf16 feats (atomic, zeroed in prep)
__device__ float g_rn[4][BN];      // 1/row-norm of c_v, s_v, c_t, s_t
__device__ __nv_bfloat16 g_nfT[4][DN * BN]; // normalized, transposed (p-major, i contig)
__device__ float g_sq[2][BN];      // row squared norms of bf16(c_v), bf16(c_t)
__device__ int   g_cls[BN];        // label*4+domain, or -1 if masked out
__device__ __nv_bfloat16 g_bf[2][BN * DN];  // bf16 copies of c_v, c_t
__device__ int   g_perm[BN];       // class-sorted permutation (gather: dest -> src)
__device__ __nv_bfloat16 g_bfS[2][BN * DN]; // class-sorted bf16 copies
__device__ float g_sqS[2][BN];     // class-sorted sq norms
__device__ int   g_clsS[BN];       // class-sorted class ids
__device__ float g_lpart[5][16];   // small-loss block partials (written)
__device__ float g_rpart[512];     // recon block partials (written)
__device__ float g_hpart[512];     // hsic frob block partials (written)
__device__ int   g_ticket;         // = 0 statically; self-resetting

__device__ __forceinline__ unsigned smem_u32(const void* p) {
    return (unsigned)__cvta_generic_to_shared(p);
}

// =======================================================================
// Kernel A: prep — grid (512, 6), 256 threads
// =======================================================================
__global__ void prep_kernel(const float* __restrict__ cv, const float* __restrict__ ct,
                            const float* __restrict__ sv, const float* __restrict__ st,
                            const int* __restrict__ lab, const int* __restrict__ dom,
                            const unsigned char* __restrict__ mask,
                            const float* __restrict__ l1, const int* __restrict__ b1,
                            const float* __restrict__ l2, const int* __restrict__ b2,
                            const float* __restrict__ l3, const int* __restrict__ b3,
                            const float* __restrict__ vsv, const float* __restrict__ vst,
                            const float* __restrict__ hir, const float* __restrict__ hio,
                            const float* __restrict__ htr, const float* __restrict__ hto) {
    int role = blockIdx.y;
    int bx = blockIdx.x;
    int tid = threadIdx.x;

    if (role == 0) {
        int r = (bx * 256 + tid) >> 5;
        int lane = tid & 31;
        #pragma unroll
        for (int set = 0; set < 2; set++) {
            const float* src = set ? ct : cv;
            const float4* p = (const float4*)(src + (size_t)r * DN);
            float4 v0 = p[lane * 2], v1 = p[lane * 2 + 1];
            float s32 = v0.x * v0.x + v0.y * v0.y + v0.z * v0.z + v0.w * v0.w
                      + v1.x * v1.x + v1.y * v1.y + v1.z * v1.z + v1.w * v1.w;
            __nv_bfloat16 t[8];
            t[0] = __float2bfloat16(v0.x); t[1] = __float2bfloat16(v0.y);
            t[2] = __float2bfloat16(v0.z); t[3] = __float2bfloat16(v0.w);
            t[4] = __float2bfloat16(v1.x); t[5] = __float2bfloat16(v1.y);
            t[6] = __float2bfloat16(v1.z); t[7] = __float2bfloat16(v1.w);
            float sbf = 0.f;
            #pragma unroll
            for (int i = 0; i < 8; i++) { float f = __bfloat162float(t[i]); sbf += f * f; }
            #pragma unroll
            for (int o = 16; o; o >>= 1) {
                s32 += __shfl_xor_sync(0xffffffffu, s32, o);
                sbf += __shfl_xor_sync(0xffffffffu, sbf, o);
            }
            if (lane == 0) {
                g_sq[set][r] = sbf;
                g_rn[set * 2][r] = 1.f / fmaxf(sqrtf(s32), 1e-12f);
            }
            *(uint4*)(g_bf[set] + (size_t)r * DN + lane * 8) = *(uint4*)t;
        }
        if (lane == 0) {
            int c = lab[r] * 4 + dom[r];
            g_cls[r] = mask[r] ? c : -1;
        }
    } else if (role <= 2) {
        const float* src = (role == 1) ? sv : st;
        int m = (role == 1) ? 1 : 3;
        int r = (bx * 256 + tid) >> 5;
        int lane = tid & 31;
        const float4* p = (const float4*)(src + (size_t)r * DN);
        float4 v0 = p[lane], v1 = p[lane + 32];
        float s = v0.x * v0.x + v0.y * v0.y + v0.z * v0.z + v0.w * v0.w
                + v1.x * v1.x + v1.y * v1.y + v1.z * v1.z + v1.w * v1.w;
        #pragma unroll
        for (int o = 16; o; o >>= 1) s += __shfl_xor_sync(0xffffffffu, s, o);
        if (lane == 0) g_rn[m][r] = 1.f / fmaxf(sqrtf(s), 1e-12f);
    } else if (role == 3) {
        const int n4 = BN * HN / 4;
        const int stride = 512 * 256;
        float s = 0.f;
        for (int i = bx * 256 + tid; i < n4; i += stride) {
            float4 va = ((const float4*)hir)[i], vb = ((const float4*)hio)[i];
            float dx = va.x - vb.x, dy = va.y - vb.y, dz = va.z - vb.z, dw = va.w - vb.w;
            s += dx * dx + dy * dy + dz * dz + dw * dw;
            float4 vc = ((const float4*)htr)[i], vd = ((const float4*)hto)[i];
            dx = vc.x - vd.x; dy = vc.y - vd.y; dz = vc.z - vd.z; dw = vc.w - vd.w;
            s += dx * dx + dy * dy + dz * dz + dw * dw;
        }
        __shared__ float red[256];
        red[tid] = s;
        __syncthreads();
        for (int st_ = 128; st_; st_ >>= 1) { if (tid < st_) red[tid] += red[tid + st_]; __syncthreads(); }
        if (tid == 0) g_rpart[bx] = red[0];
    } else if (role == 4) {
        if (bx >= 80) return;
        int task = bx >> 4, sub = bx & 15;
        int r = sub * 256 + tid;
        float loss = 0.f;
        if (mask[r]) {
            if (task < 3) {
                const float* lg = (task == 0) ? l1 : (task == 1) ? l2 : l3;
                const int* lb = (task == 0) ? b1 : (task == 1) ? b2 : b3;
                int nc = (task == 0) ? 4 : (task == 1) ? 6 : 3;
                float x[6];
                float mx = -1e30f;
                for (int c = 0; c < nc; c++) { x[c] = lg[r * nc + c]; mx = fmaxf(mx, x[c]); }
                float se = 0.f, sx = 0.f;
                for (int c = 0; c < nc; c++) { se += expf(x[c] - mx); sx += x[c]; }
                float logZ = mx + logf(se);
                int t = lb[r];
                float ce = logZ - (0.9f * x[t] + (0.1f / (float)nc) * sx);
                float pt = expf(x[t] - logZ);
                float om = 1.f - pt;
                loss = ce * om * om;
            } else {
                const float* lg = (task == 3) ? vsv : vst;
                float x0 = lg[r * 4 + 0], x1 = lg[r * 4 + 1], x2 = lg[r * 4 + 2], x3 = lg[r * 4 + 3];
                float mx = fmaxf(fmaxf(x0, x1), fmaxf(x2, x3));
                float se = expf(x0 - mx) + expf(x1 - mx) + expf(x2 - mx) + expf(x3 - mx);
                float logZ = mx + logf(se);
                int t = dom[r];
                float xt = (t == 0) ? x0 : (t == 1) ? x1 : (t == 2) ? x2 : x3;
                loss = logZ - xt;
            }
        }
        __shared__ float red[256];
        red[tid] = loss;
        __syncthreads();
        for (int st_ = 128; st_; st_ >>= 1) { if (tid < st_) red[tid] += red[tid + st_]; __syncthreads(); }
        if (tid == 0) g_lpart[task][sub] = red[0];
    } else {
        // zero g_M: 131072 elems over 512 blocks x 256 thr = exactly 1 each
        ((float*)g_M)[bx * 256 + tid] = 0.f;
        if (bx == 0) { for (int e = tid; e < 512; e += 256) ((float*)g_G)[e] = 0.f; }
        else if (bx == 1) { for (int e = tid; e < 1024; e += 256) ((float*)g_colsum)[e] = 0.f; }
    }
}

// =======================================================================
// Kernel S: counting sort of rows by class (1 block)
// =======================================================================
__global__ void sort_kernel() {
    __shared__ int cnt[16];
    __shared__ int rank[17];
    int tid = threadIdx.x;
    if (tid < 16) cnt[tid] = 0;
    __syncthreads();
    int myc[16];
    #pragma unroll
    for (int it = 0; it < 16; it++) {
        int c = g_cls[it * 256 + tid];
        myc[it] = c;
        if (c >= 0) atomicAdd(&cnt[c], 1);
    }
    __syncthreads();
    if (tid == 0) {
        int acc = 0;
        for (int k = 0; k < 16; k++) { rank[k] = acc; acc += cnt[k]; }
        rank[16] = acc;               // masked-out rows go at the end
    }
    __syncthreads();
    #pragma unroll
    for (int it = 0; it < 16; it++) {
        int r = it * 256 + tid;
        int c = myc[it];
        int pos = atomicAdd(&rank[(c >= 0) ? c : 16], 1);
        g_perm[pos] = r;
    }
}

// =======================================================================
// Kernel B: z<4: normalize + transpose + colsums;  z==4: permute sorted copies
// =======================================================================
__global__ void transposeN_kernel(const float* __restrict__ in0, const float* __restrict__ in1,
                                  const float* __restrict__ in2, const float* __restrict__ in3) {
    int tid = threadIdx.x;
    if (blockIdx.z == 4) {
        // permute: 256 blocks (bx 0..63, by 0..3), 16 dest rows each
        int idx = blockIdx.y * 64 + blockIdx.x;
        int rl = tid >> 4, t16 = tid & 15;
        int d = idx * 16 + rl;
        int src = g_perm[d];
        const uint4* s0 = (const uint4*)(g_bf[0] + (size_t)src * DN);
        uint4* d0 = (uint4*)(g_bfS[0] + (size_t)d * DN);
        d0[t16] = s0[t16];
        d0[t16 + 16] = s0[t16 + 16];
        const uint4* s1 = (const uint4*)(g_bf[1] + (size_t)src * DN);
        uint4* d1 = (uint4*)(g_bfS[1] + (size_t)d * DN);
        d1[t16] = s1[t16];
        d1[t16 + 16] = s1[t16 + 16];
        if (t16 == 0) {
            g_sqS[0][d] = g_sq[0][src];
            g_sqS[1][d] = g_sq[1][src];
            g_clsS[d] = g_cls[src];
        }
        return;
    }
    int m = blockIdx.z;
    const float* src = (m == 0) ? in0 : (m == 1) ? in1 : (m == 2) ? in2 : in3;
    __nv_bfloat16* dst = g_nfT[m];
    int i0 = blockIdx.x * 64, p0 = blockIdx.y * 64;

    __shared__ __nv_bfloat16 smT[64][88];
    __shared__ float rns[64];
    if (tid < 64) rns[tid] = g_rn[m][i0 + tid];
    __syncthreads();

    #pragma unroll
    for (int s = tid; s < 1024; s += 256) {
        int r = s >> 4, c4 = (s & 15) * 4;
        float4 v = *(const float4*)(src + (size_t)(i0 + r) * DN + p0 + c4);
        float rn = rns[r];
        smT[c4 + 0][r] = __float2bfloat16(v.x * rn);
        smT[c4 + 1][r] = __float2bfloat16(v.y * rn);
        smT[c4 + 2][r] = __float2bfloat16(v.z * rn);
        smT[c4 + 3][r] = __float2bfloat16(v.w * rn);
    }
    __syncthreads();
    #pragma unroll
    for (int s = tid; s < 512; s += 256) {
        int pl = s >> 3, i8 = (s & 7) * 8;
        *(uint4*)(dst + (size_t)(p0 + pl) * BN + i0 + i8) = *(uint4*)&smT[pl][i8];
    }
    if (tid < 64) {
        float s = 0.f;
        #pragma unroll
        for (int i = 0; i < 64; i++) s += __bfloat162float(smT[tid][i]);
        atomicAdd(&g_colsum[m][p0 + tid], s);
    }
}

// =======================================================================
// Kernel CD: gram (blocks 0..1055, class-sorted data) + hsic_mma (1056..1183)
// =======================================================================
#define PITCH 72
#define KC 64

__global__ __launch_bounds__(256) void gram_hsic_kernel() {
    __shared__ __nv_bfloat16 As[128 * PITCH];
    __shared__ __nv_bfloat16 Bs[128 * PITCH];
    __shared__ float bins[8][256];
    __shared__ float sqi[128], sqj[128];
    __shared__ int   ci_s[128], cj_s[128];

    int tid = threadIdx.x;
    int wid = tid >> 5, lane = tid & 31;
    int wm = wid >> 2, wn = wid & 3;
    unsigned as_base = smem_u32(As);
    unsigned bs_base = smem_u32(Bs);

    float acc[4][4][4];
    #pragma unroll
    for (int mi = 0; mi < 4; mi++)
        #pragma unroll
        for (int ni = 0; ni < 4; ni++)
            #pragma unroll
            for (int r = 0; r < 4; r++) acc[mi][ni][r] = 0.f;

    if (blockIdx.x < 1056) {
        // ---------------- GRAM path (sorted data) ----------------
        const int T = BN / 128;
        int set = (blockIdx.x >= 528) ? 1 : 0;
        int idx = blockIdx.x - set * 528;
        const __nv_bfloat16* X = g_bfS[set];
        int ti = 0;
        while (idx >= T - ti) { idx -= T - ti; ti++; }
        int tj = ti + idx;
        int i0 = ti * 128, j0 = tj * 128;
        bool diag = (ti == tj);

        for (int b = tid; b < 2048; b += 256) ((float*)bins)[b] = 0.f;
        if (tid < 128) { sqi[tid] = g_sqS[set][i0 + tid]; ci_s[tid] = g_clsS[i0 + tid]; }
        else { int t = tid - 128; sqj[t] = g_sqS[set][j0 + t]; cj_s[t] = g_clsS[j0 + t]; }

        for (int kc = 0; kc < DN; kc += KC) {
            __syncthreads();
            #pragma unroll
            for (int p = 0; p < 4; p++) {
                int v = tid + p * 256;
                int row = v >> 3, c8 = v & 7;
                uint4 da = *(const uint4*)(X + (size_t)(i0 + row) * DN + kc + c8 * 8);
                *(uint4*)(As + row * PITCH + c8 * 8) = da;
                uint4 db = *(const uint4*)(X + (size_t)(j0 + row) * DN + kc + c8 * 8);
                *(uint4*)(Bs + row * PITCH + c8 * 8) = db;
            }
            __syncthreads();
            #pragma unroll
            for (int ks = 0; ks < KC; ks += 16) {
                unsigned a[4][4], b[4][2];
                #pragma unroll
                for (int mi = 0; mi < 4; mi++) {
                    int row = wm * 64 + mi * 16 + (lane & 15);
                    unsigned addr = as_base + (row * PITCH + ks + (lane >> 4) * 8) * 2;
                    asm volatile("ldmatrix.sync.aligned.m8n8.x4.shared.b16 {%0,%1,%2,%3}, [%4];"
                                 : "=r"(a[mi][0]), "=r"(a[mi][1]), "=r"(a[mi][2]), "=r"(a[mi][3])
                                 : "r"(addr));
                }
                #pragma unroll
                for (int p = 0; p < 2; p++) {
                    int g = lane >> 3, r = lane & 7;
                    int row = wn * 32 + p * 16 + (g >> 1) * 8 + r;
                    unsigned addr = bs_base + (row * PITCH + ks + (g & 1) * 8) * 2;
                    unsigned r0, r1, r2, r3;
                    asm volatile("ldmatrix.sync.aligned.m8n8.x4.shared.b16 {%0,%1,%2,%3}, [%4];"
                                 : "=r"(r0), "=r"(r1), "=r"(r2), "=r"(r3) : "r"(addr));
                    b[p * 2][0] = r0;  b[p * 2][1] = r1;
                    b[p * 2 + 1][0] = r2;  b[p * 2 + 1][1] = r3;
                }
                #pragma unroll
                for (int mi = 0; mi < 4; mi++)
                    #pragma unroll
                    for (int ni = 0; ni < 4; ni++) {
                        asm volatile(
                            "mma.sync.aligned.m16n8k16.row.col.f32.bf16.bf16.f32 "
                            "{%0,%1,%2,%3}, {%4,%5,%6,%7}, {%8,%9}, {%0,%1,%2,%3};"
                            : "+f"(acc[mi][ni][0]), "+f"(acc[mi][ni][1]),
                              "+f"(acc[mi][ni][2]), "+f"(acc[mi][ni][3])
                            : "r"(a[mi][0]), "r"(a[mi][1]), "r"(a[mi][2]), "r"(a[mi][3]),
                              "r"(b[ni][0]), "r"(b[ni][1]));
                    }
            }
        }

        // epilogue: run-length accumulation into one pending bin (sorted classes)
        {
            int pkey = -1;
            float pend = 0.f;
            #pragma unroll
            for (int mi = 0; mi < 4; mi++) {
                #pragma unroll
                for (int rr = 0; rr < 2; rr++) {
                    int il = wm * 64 + mi * 16 + (lane >> 2) + rr * 8;
                    int aCls = ci_s[il];
                    if (aCls < 0) continue;
                    float si = sqi[il];
                    #pragma unroll
                    for (int ni = 0; ni < 4; ni++) {
                        #pragma unroll
                        for (int cc = 0; cc < 2; cc++) {
                            int jl = wn * 32 + ni * 8 + (lane & 3) * 2 + cc;
                            int bCls = cj_s[jl];
                            if (bCls < 0) continue;
                            float Kv;
                            if (diag && jl <= il) {
                                if (jl < il) continue;
                                Kv = 2.5f;                    // exact K(i,i)=5, single-counted
                            } else {
                                float dot = acc[mi][ni][rr * 2 + cc];
                                float D = si + sqj[jl] - 2.f * dot;
                                Kv = __expf(-0.01f * D);
                                if (D < 340.f) {
                                    Kv += __expf(-0.1f * D) + __expf(-D)
                                        + __expf(-10.f * D) + __expf(-100.f * D);
                                }
                            }
                            int key = aCls * 16 + bCls;
                            if (key == pkey) {
                                pend += Kv;
                            } else {
                                if (pkey >= 0) atomicAdd(&bins[wid][pkey], pend);
                                pkey = key;
                                pend = Kv;
                            }
                        }
                    }
                }
            }
            if (pkey >= 0) atomicAdd(&bins[wid][pkey], pend);
        }
        __syncthreads();
        {
            float s = 0.f;
            #pragma unroll
            for (int w = 0; w < 8; w++) s += bins[w][tid];
            atomicAdd(&g_G[set][tid], s);
        }
    } else {
        // ---------------- HSIC MMA path (RED-accumulated into g_M) ----------------
        int b2 = blockIdx.x - 1056;
        int tile = b2 & 3, split = (b2 >> 2) & 15, pair = b2 >> 6;
        int tp = (tile >> 1) * 128, tq = (tile & 1) * 128;
        int k0 = split * 256;
        const __nv_bfloat16* A = g_nfT[2 * pair];
        const __nv_bfloat16* Bm = g_nfT[2 * pair + 1];
        float* out = g_M[pair];

        for (int kc = 0; kc < 256; kc += KC) {
            __syncthreads();
            #pragma unroll
            for (int p = 0; p < 4; p++) {
                int v = tid + p * 256;
                int row = v >> 3, c8 = v & 7;
                uint4 da = *(const uint4*)(A + (size_t)(tp + row) * BN + k0 + kc + c8 * 8);
                *(uint4*)(As + row * PITCH + c8 * 8) = da;
                uint4 db = *(const uint4*)(Bm + (size_t)(tq + row) * BN + k0 + kc + c8 * 8);
                *(uint4*)(Bs + row * PITCH + c8 * 8) = db;
            }
            __syncthreads();
            #pragma unroll
            for (int ks = 0; ks < KC; ks += 16) {
                unsigned a[4][4], b[4][2];
                #pragma unroll
                for (int mi = 0; mi < 4; mi++) {
                    int row = wm * 64 + mi * 16 + (lane & 15);
                    unsigned addr = as_base + (row * PITCH + ks + (lane >> 4) * 8) * 2;
                    asm volatile("ldmatrix.sync.aligned.m8n8.x4.shared.b16 {%0,%1,%2,%3}, [%4];"
                                 : "=r"(a[mi][0]), "=r"(a[mi][1]), "=r"(a[mi][2]), "=r"(a[mi][3])
                                 : "r"(addr));
                }
                #pragma unroll
                for (int p = 0; p < 2; p++) {
                    int g = lane >> 3, r = lane & 7;
                    int row = wn * 32 + p * 16 + (g >> 1) * 8 + r;
                    unsigned addr = bs_base + (row * PITCH + ks + (g & 1) * 8) * 2;
                    unsigned r0, r1, r2, r3;
                    asm volatile("ldmatrix.sync.aligned.m8n8.x4.shared.b16 {%0,%1,%2,%3}, [%4];"
                                 : "=r"(r0), "=r"(r1), "=r"(r2), "=r"(r3) : "r"(addr));
                    b[p * 2][0] = r0;  b[p * 2][1] = r1;
                    b[p * 2 + 1][0] = r2;  b[p * 2 + 1][1] = r3;
                }
                #pragma unroll
                for (int mi = 0; mi < 4; mi++)
                    #pragma unroll
                    for (int ni = 0; ni < 4; ni++) {
                        asm volatile(
                            "mma.sync.aligned.m16n8k16.row.col.f32.bf16.bf16.f32 "
                            "{%0,%1,%2,%3}, {%4,%5,%6,%7}, {%8,%9}, {%0,%1,%2,%3};"
                            : "+f"(acc[mi][ni][0]), "+f"(acc[mi][ni][1]),
                              "+f"(acc[mi][ni][2]), "+f"(acc[mi][ni][3])
                            : "r"(a[mi][0]), "r"(a[mi][1]), "r"(a[mi][2]), "r"(a[mi][3]),
                              "r"(b[ni][0]), "r"(b[ni][1]));
                    }
            }
        }

        #pragma unroll
        for (int mi = 0; mi < 4; mi++)
            #pragma unroll
            for (int ni = 0; ni < 4; ni++)
                #pragma unroll
                for (int rr = 0; rr < 2; rr++) {
                    int row = tp + wm * 64 + mi * 16 + (lane >> 2) + rr * 8;
                    int col = tq + wn * 32 + ni * 8 + (lane & 3) * 2;
                    atomicAdd(&out[row * 256 + col], acc[mi][ni][rr * 2]);
                    atomicAdd(&out[row * 256 + col + 1], acc[mi][ni][rr * 2 + 1]);
                }
    }
}

// =======================================================================
// Kernel E: hsic reduce (512 blocks, 1 elem/thread over 512KB)
//           + last-block PARALLEL combine
// =======================================================================
__global__ void reduce_combine_kernel(float* __restrict__ out) {
    int tid = threadIdx.x;
    int bx = blockIdx.x;
    const float invB = 1.f / (float)BN;
    __shared__ float red[256];

    int g = bx * 256 + tid;              // 131072 threads total
    int pair = g >> 16;
    int e = g & 65535;
    int p = e >> 8, q = e & 255;
    float s0 = g_M[pair][e];
    float cp = (pair == 0) ? g_colsum[0][p] : g_colsum[2][p];
    float cq = (pair == 0) ? g_colsum[1][q] : g_colsum[3][q];
    float m0 = s0 - cp * cq * invB;
    red[tid] = m0 * m0;
    __syncthreads();
    for (int s = 128; s; s >>= 1) { if (tid < s) red[tid] += red[tid + s]; __syncthreads(); }
    if (tid == 0) g_hpart[bx] = red[0];
    __threadfence();

    __shared__ int is_last;
    if (tid == 0) {
        int t = atomicAdd(&g_ticket, 1);
        is_last = (t == 511) ? 1 : 0;
    }
    __syncthreads();
    if (!is_last) return;
    if (tid == 0) g_ticket = 0;     // self-reset for next replay

    // ---- last block: cooperative staging into smem, then parallel combine ----
    __shared__ float sh_G[512];      // both 16x16 histograms
    __shared__ float sh_ls[5];       // small-loss sums
    __shared__ float cntS[16];
    __shared__ float sh_mmd[2];
    __shared__ float sh_cnt2[2];

    sh_G[tid] = ((const float*)g_G)[tid];
    sh_G[tid + 256] = ((const float*)g_G)[tid + 256];
    if (tid < 16) cntS[tid] = 0.f;
    if (tid < 5) sh_ls[tid] = 0.f;
    if (tid < 2) { sh_mmd[tid] = 0.f; sh_cnt2[tid] = 0.f; }
    __syncthreads();

    for (int r = tid; r < BN; r += 256) {
        int c = g_cls[r];
        if (c >= 0) atomicAdd(&cntS[c], 1.f);
    }
    if (tid < 80) atomicAdd(&sh_ls[tid >> 4], g_lpart[tid >> 4][tid & 15]);

    float hp = g_hpart[tid] + g_hpart[tid + 256];
    float rp = g_rpart[tid] + g_rpart[tid + 256];
    __syncthreads();   // cntS, sh_G ready before mmd terms

    if (tid < 48) {
        int s = tid / 24, r2 = tid % 24;
        int lab = r2 / 6, pr = r2 % 6;
        int d1 = (pr < 3) ? 0 : (pr < 5) ? 1 : 2;
        int d2 = (pr < 3) ? pr + 1 : (pr < 5) ? pr - 1 : 3;
        int a = lab * 4 + d1, b = lab * 4 + d2;
        float n1 = cntS[a], n2 = cntS[b];
        if (n1 > 1.f && n2 > 1.f) {
            const float* G = sh_G + s * 256;
            float ga = 2.f * G[a * 16 + a];
            float gb = 2.f * G[b * 16 + b];
            float gab = G[a * 16 + b] + G[b * 16 + a];
            float m1m = fmaxf(n1, 1.f), m2m = fmaxf(n2, 1.f);
            float term = ga / (m1m * m1m) + gb / (m2m * m2m)
                       - 2.f * gab / fmaxf(n1 * n2, 1.f);
            atomicAdd(&sh_mmd[s], term);
            atomicAdd(&sh_cnt2[s], 1.f);
        }
    }

    red[tid] = hp;
    __syncthreads();
    for (int s = 128; s; s >>= 1) { if (tid < s) red[tid] += red[tid + s]; __syncthreads(); }
    float hsic_frob = red[0];
    __syncthreads();
    red[tid] = rp;
    __syncthreads();
    for (int s = 128; s; s >>= 1) { if (tid < s) red[tid] += red[tid + s]; __syncthreads(); }
    float recon_sum = red[0];
    __syncthreads();

    if (tid == 0) {
        float hsic_sum = hsic_frob / (4095.f * 4095.f);
        float mmd0 = sh_mmd[0] / fmaxf(sh_cnt2[0], 1.f);
        float mmd1 = sh_mmd[1] / fmaxf(sh_cnt2[1], 1.f);
        float msum = 0.f;
        #pragma unroll
        for (int k = 0; k < 16; k++) msum += cntS[k];
        msum = fmaxf(msum, 1.f);

        float total = 0.4f * sh_ls[0] / msum + 0.3f * sh_ls[1] / msum + 0.3f * sh_ls[2] / msum;
        total += 0.1f * (sh_ls[3] / msum + sh_ls[4] / msum + mmd0 + mmd1);
        total += 0.1f * hsic_sum;
        total += recon_sum / (float)(BN * HN);
        out[0] = total;
    }
}

// ---------------- launch ----------------
extern "C" void kernel_launch(void* const* d_in, const int* in_sizes, int n_in,
                              void* d_out, int out_size) {
    (void)in_sizes; (void)n_in; (void)out_size;
    const float* logits1 = (const float*)d_in[0];
    const int*   labels1 = (const int*)d_in[1];
    const float* logits2 = (const float*)d_in[2];
    const int*   labels2 = (const int*)d_in[3];
    const float* logits3 = (const float*)d_in[4];
    const int*   labels3 = (const int*)d_in[5];
    const float* c_v  = (const float*)d_in[6];
    const float* s_v  = (const float*)d_in[7];
    const float* c_t  = (const float*)d_in[8];
    const float* s_t  = (const float*)d_in[9];
    const float* v_sv = (const float*)d_in[10];
    const float* v_st = (const float*)d_in[11];
    const int*   dom  = (const int*)d_in[12];
    const unsigned char* mask = (const unsigned char*)d_in[13];
    const float* hir = (const float*)d_in[14];
    const float* hio = (const float*)d_in[15];
    const float* htr = (const float*)d_in[16];
    const float* hto = (const float*)d_in[17];

    prep_kernel<<<dim3(512, 6), 256>>>(c_v, c_t, s_v, s_t, labels1, dom, mask,
                                       logits1, labels1, logits2, labels2, logits3, labels3,
                                       v_sv, v_st, hir, hio, htr, hto);
    sort_kernel<<<1, 256>>>();
    transposeN_kernel<<<dim3(64, 4, 5), 256>>>(c_v, s_v, c_t, s_t);
    gram_hsic_kernel<<<1184, 256>>>();
    reduce_combine_kernel<<<512, 256>>>((float*)d_out);
}

// round 14
// speedup vs baseline: 1.0758x; 1.0758x over previous
#include <cuda_runtime.h>
#include <cuda_bf16.h>
#include <math.h>

#define BN 4096
#define DN 256
#define HN 768

// ---------------- device scratch (static, allocation-free) ----------------
__device__ float g_G[2][256];      // single-counted 16x16 Ksum histograms (atomic, zeroed in prep)
__device__ float g_M[2][65536];    // HSIC cross products (RED-accumulated, zeroed in prep)
__device__ float g_colsum[4][256]; // column sums of normalized bf16 feats (atomic, zeroed in prep)
__device__ float g_rn[4][BN];      // 1/row-norm of c_v, s_v, c_t, s_t
__device__ __nv_bfloat16 g_nfT[4][DN * BN]; // normalized, transposed (p-major, i contig)
__device__ float g_sq[2][BN];      // row squared norms of bf16(c_v), bf16(c_t)
__device__ int   g_cls[BN];        // label*4+domain, or -1 if masked out
__device__ __nv_bfloat16 g_bf[2][BN * DN];  // bf16 copies of c_v, c_t
__device__ float g_lpart[5][16];   // small-loss block partials (written)
__device__ float g_rpart[512];     // recon block partials (written)
__device__ float g_hpart[512];     // hsic frob block partials (written)
__device__ int   g_ticket;         // = 0 statically; self-resetting

__device__ __forceinline__ unsigned smem_u32(const void* p) {
    return (unsigned)__cvta_generic_to_shared(p);
}

// =======================================================================
// Kernel A: prep — grid (512, 6), 256 threads
// =======================================================================
__global__ void prep_kernel(const float* __restrict__ cv, const float* __restrict__ ct,
                            const float* __restrict__ sv, const float* __restrict__ st,
                            const int* __restrict__ lab, const int* __restrict__ dom,
                            const unsigned char* __restrict__ mask,
                            const float* __restrict__ l1, const int* __restrict__ b1,
                            const float* __restrict__ l2, const int* __restrict__ b2,
                            const float* __restrict__ l3, const int* __restrict__ b3,
                            const float* __restrict__ vsv, const float* __restrict__ vst,
                            const float* __restrict__ hir, const float* __restrict__ hio,
                            const float* __restrict__ htr, const float* __restrict__ hto) {
    int role = blockIdx.y;
    int bx = blockIdx.x;
    int tid = threadIdx.x;

    if (role == 0) {
        int r = (bx * 256 + tid) >> 5;
        int lane = tid & 31;
        #pragma unroll
        for (int set = 0; set < 2; set++) {
            const float* src = set ? ct : cv;
            const float4* p = (const float4*)(src + (size_t)r * DN);
            float4 v0 = p[lane * 2], v1 = p[lane * 2 + 1];
            float s32 = v0.x * v0.x + v0.y * v0.y + v0.z * v0.z + v0.w * v0.w
                      + v1.x * v1.x + v1.y * v1.y + v1.z * v1.z + v1.w * v1.w;
            __nv_bfloat16 t[8];
            t[0] = __float2bfloat16(v0.x); t[1] = __float2bfloat16(v0.y);
            t[2] = __float2bfloat16(v0.z); t[3] = __float2bfloat16(v0.w);
            t[4] = __float2bfloat16(v1.x); t[5] = __float2bfloat16(v1.y);
            t[6] = __float2bfloat16(v1.z); t[7] = __float2bfloat16(v1.w);
            float sbf = 0.f;
            #pragma unroll
            for (int i = 0; i < 8; i++) { float f = __bfloat162float(t[i]); sbf += f * f; }
            #pragma unroll
            for (int o = 16; o; o >>= 1) {
                s32 += __shfl_xor_sync(0xffffffffu, s32, o);
                sbf += __shfl_xor_sync(0xffffffffu, sbf, o);
            }
            if (lane == 0) {
                g_sq[set][r] = sbf;
                g_rn[set * 2][r] = 1.f / fmaxf(sqrtf(s32), 1e-12f);
            }
            *(uint4*)(g_bf[set] + (size_t)r * DN + lane * 8) = *(uint4*)t;
        }
        if (lane == 0) {
            int c = lab[r] * 4 + dom[r];
            g_cls[r] = mask[r] ? c : -1;
        }
    } else if (role <= 2) {
        const float* src = (role == 1) ? sv : st;
        int m = (role == 1) ? 1 : 3;
        int r = (bx * 256 + tid) >> 5;
        int lane = tid & 31;
        const float4* p = (const float4*)(src + (size_t)r * DN);
        float4 v0 = p[lane], v1 = p[lane + 32];
        float s = v0.x * v0.x + v0.y * v0.y + v0.z * v0.z + v0.w * v0.w
                + v1.x * v1.x + v1.y * v1.y + v1.z * v1.z + v1.w * v1.w;
        #pragma unroll
        for (int o = 16; o; o >>= 1) s += __shfl_xor_sync(0xffffffffu, s, o);
        if (lane == 0) g_rn[m][r] = 1.f / fmaxf(sqrtf(s), 1e-12f);
    } else if (role == 3) {
        const int n4 = BN * HN / 4;
        const int stride = 512 * 256;
        float s = 0.f;
        for (int i = bx * 256 + tid; i < n4; i += stride) {
            float4 va = ((const float4*)hir)[i], vb = ((const float4*)hio)[i];
            float dx = va.x - vb.x, dy = va.y - vb.y, dz = va.z - vb.z, dw = va.w - vb.w;
            s += dx * dx + dy * dy + dz * dz + dw * dw;
            float4 vc = ((const float4*)htr)[i], vd = ((const float4*)hto)[i];
            dx = vc.x - vd.x; dy = vc.y - vd.y; dz = vc.z - vd.z; dw = vc.w - vd.w;
            s += dx * dx + dy * dy + dz * dz + dw * dw;
        }
        __shared__ float red[256];
        red[tid] = s;
        __syncthreads();
        for (int st_ = 128; st_; st_ >>= 1) { if (tid < st_) red[tid] += red[tid + st_]; __syncthreads(); }
        if (tid == 0) g_rpart[bx] = red[0];
    } else if (role == 4) {
        if (bx >= 80) return;
        int task = bx >> 4, sub = bx & 15;
        int r = sub * 256 + tid;
        float loss = 0.f;
        if (mask[r]) {
            if (task < 3) {
                const float* lg = (task == 0) ? l1 : (task == 1) ? l2 : l3;
                const int* lb = (task == 0) ? b1 : (task == 1) ? b2 : b3;
                int nc = (task == 0) ? 4 : (task == 1) ? 6 : 3;
                float x[6];
                float mx = -1e30f;
                for (int c = 0; c < nc; c++) { x[c] = lg[r * nc + c]; mx = fmaxf(mx, x[c]); }
                float se = 0.f, sx = 0.f;
                for (int c = 0; c < nc; c++) { se += expf(x[c] - mx); sx += x[c]; }
                float logZ = mx + logf(se);
                int t = lb[r];
                float ce = logZ - (0.9f * x[t] + (0.1f / (float)nc) * sx);
                float pt = expf(x[t] - logZ);
                float om = 1.f - pt;
                loss = ce * om * om;
            } else {
                const float* lg = (task == 3) ? vsv : vst;
                float x0 = lg[r * 4 + 0], x1 = lg[r * 4 + 1], x2 = lg[r * 4 + 2], x3 = lg[r * 4 + 3];
                float mx = fmaxf(fmaxf(x0, x1), fmaxf(x2, x3));
                float se = expf(x0 - mx) + expf(x1 - mx) + expf(x2 - mx) + expf(x3 - mx);
                float logZ = mx + logf(se);
                int t = dom[r];
                float xt = (t == 0) ? x0 : (t == 1) ? x1 : (t == 2) ? x2 : x3;
                loss = logZ - xt;
            }
        }
        __shared__ float red[256];
        red[tid] = loss;
        __syncthreads();
        for (int st_ = 128; st_; st_ >>= 1) { if (tid < st_) red[tid] += red[tid + st_]; __syncthreads(); }
        if (tid == 0) g_lpart[task][sub] = red[0];
    } else {
        // zero g_M: 131072 elems over 512 blocks x 256 thr = exactly 1 each
        ((float*)g_M)[bx * 256 + tid] = 0.f;
        if (bx == 0) { for (int e = tid; e < 512; e += 256) ((float*)g_G)[e] = 0.f; }
        else if (bx == 1) { for (int e = tid; e < 1024; e += 256) ((float*)g_colsum)[e] = 0.f; }
    }
}

// =======================================================================
// Kernel B: normalize + transpose to bf16 (p-major) + fused column sums
// =======================================================================
__global__ void transposeN_kernel(const float* __restrict__ in0, const float* __restrict__ in1,
                                  const float* __restrict__ in2, const float* __restrict__ in3) {
    int m = blockIdx.z;
    const float* src = (m == 0) ? in0 : (m == 1) ? in1 : (m == 2) ? in2 : in3;
    __nv_bfloat16* dst = g_nfT[m];
    int i0 = blockIdx.x * 64, p0 = blockIdx.y * 64;

    __shared__ __nv_bfloat16 smT[64][88];
    __shared__ float rns[64];
    int tid = threadIdx.x;
    if (tid < 64) rns[tid] = g_rn[m][i0 + tid];
    __syncthreads();

    #pragma unroll
    for (int s = tid; s < 1024; s += 256) {
        int r = s >> 4, c4 = (s & 15) * 4;
        float4 v = *(const float4*)(src + (size_t)(i0 + r) * DN + p0 + c4);
        float rn = rns[r];
        smT[c4 + 0][r] = __float2bfloat16(v.x * rn);
        smT[c4 + 1][r] = __float2bfloat16(v.y * rn);
        smT[c4 + 2][r] = __float2bfloat16(v.z * rn);
        smT[c4 + 3][r] = __float2bfloat16(v.w * rn);
    }
    __syncthreads();
    #pragma unroll
    for (int s = tid; s < 512; s += 256) {
        int pl = s >> 3, i8 = (s & 7) * 8;
        *(uint4*)(dst + (size_t)(p0 + pl) * BN + i0 + i8) = *(uint4*)&smT[pl][i8];
    }
    if (tid < 64) {
        float s = 0.f;
        #pragma unroll
        for (int i = 0; i < 64; i++) s += __bfloat162float(smT[tid][i]);
        atomicAdd(&g_colsum[m][p0 + tid], s);
    }
}

// =======================================================================
// Kernel CD: gram (0..1055) + hsic_mma (1056..1183), cp.async double-buffered
// =======================================================================
#define PITCH 72
#define KC 64
#define TILE_B (128 * PITCH * 2)        // 18432 bytes per tile stage
#define OFF_BS (2 * TILE_B)             // Bs stages after 2 As stages
#define OFF_BINS (4 * TILE_B)           // 73728
#define OFF_SQI (OFF_BINS + 8192)       // 81920
#define OFF_SQJ (OFF_SQI + 512)
#define OFF_CI  (OFF_SQJ + 512)
#define OFF_CJ  (OFF_CI + 512)
#define SMEM_CD (OFF_CJ + 512)          // 83968

__device__ __forceinline__ void cp_tile(unsigned dst, const __nv_bfloat16* src,
                                        size_t rstride, int tid) {
    #pragma unroll
    for (int p = 0; p < 4; p++) {
        int v = tid + p * 256;
        int row = v >> 3, c8 = v & 7;
        const void* g = src + (size_t)row * rstride + c8 * 8;
        unsigned s = dst + (unsigned)((row * PITCH + c8 * 8) * 2);
        asm volatile("cp.async.cg.shared.global [%0], [%1], 16;" :: "r"(s), "l"(g));
    }
}

__global__ void __launch_bounds__(256) gram_hsic_kernel() {
    extern __shared__ char dyn[];
    float* bins = (float*)(dyn + OFF_BINS);        // [8][256]
    float* sqi = (float*)(dyn + OFF_SQI);
    float* sqj = (float*)(dyn + OFF_SQJ);
    int*   ci_s = (int*)(dyn + OFF_CI);
    int*   cj_s = (int*)(dyn + OFF_CJ);

    int tid = threadIdx.x;
    int wid = tid >> 5, lane = tid & 31;
    int wm = wid >> 2, wn = wid & 3;
    unsigned asb = smem_u32(dyn);
    unsigned bsb = asb + OFF_BS;

    float acc[4][4][4];
    #pragma unroll
    for (int mi = 0; mi < 4; mi++)
        #pragma unroll
        for (int ni = 0; ni < 4; ni++)
            #pragma unroll
            for (int r = 0; r < 4; r++) acc[mi][ni][r] = 0.f;

    bool isGram = (blockIdx.x < 1056);
    const __nv_bfloat16 *srcA, *srcB;
    size_t rstride;
    int i0 = 0, j0 = 0;
    bool diag = false;
    int set = 0, pair = 0, tp = 0, tq = 0;

    if (isGram) {
        const int T = BN / 128;
        set = (blockIdx.x >= 528) ? 1 : 0;
        int idx = blockIdx.x - set * 528;
        int ti = 0;
        while (idx >= T - ti) { idx -= T - ti; ti++; }
        int tj = ti + idx;
        i0 = ti * 128; j0 = tj * 128;
        diag = (ti == tj);
        srcA = g_bf[set] + (size_t)i0 * DN;
        srcB = g_bf[set] + (size_t)j0 * DN;
        rstride = DN;

        for (int b = tid; b < 2048; b += 256) bins[b] = 0.f;
        if (tid < 128) { sqi[tid] = g_sq[set][i0 + tid]; ci_s[tid] = g_cls[i0 + tid]; }
        else { int t = tid - 128; sqj[t] = g_sq[set][j0 + t]; cj_s[t] = g_cls[j0 + t]; }
    } else {
        int b2 = blockIdx.x - 1056;
        int tile = b2 & 3, split = (b2 >> 2) & 15;
        pair = b2 >> 6;
        tp = (tile >> 1) * 128; tq = (tile & 1) * 128;
        int k0 = split * 256;
        srcA = g_nfT[2 * pair] + (size_t)tp * BN + k0;
        srcB = g_nfT[2 * pair + 1] + (size_t)tq * BN + k0;
        rstride = BN;
    }

    // ---- double-buffered mainloop (4 iterations of KC=64) ----
    cp_tile(asb, srcA, rstride, tid);
    cp_tile(bsb, srcB, rstride, tid);
    asm volatile("cp.async.commit_group;" ::: "memory");

    for (int kc = 0; kc < 4; kc++) {
        if (kc < 3) {
            unsigned st = ((kc + 1) & 1) * TILE_B;
            cp_tile(asb + st, srcA + (kc + 1) * KC, rstride, tid);
            cp_tile(bsb + st, srcB + (kc + 1) * KC, rstride, tid);
            asm volatile("cp.async.commit_group;" ::: "memory");
            asm volatile("cp.async.wait_group 1;" ::: "memory");
        } else {
            asm volatile("cp.async.wait_group 0;" ::: "memory");
        }
        __syncthreads();
        unsigned as_base = asb + (kc & 1) * TILE_B;
        unsigned bs_base = bsb + (kc & 1) * TILE_B;

        #pragma unroll
        for (int ks = 0; ks < KC; ks += 16) {
            unsigned a[4][4], b[4][2];
            #pragma unroll
            for (int mi = 0; mi < 4; mi++) {
                int row = wm * 64 + mi * 16 + (lane & 15);
                unsigned addr = as_base + (row * PITCH + ks + (lane >> 4) * 8) * 2;
                asm volatile("ldmatrix.sync.aligned.m8n8.x4.shared.b16 {%0,%1,%2,%3}, [%4];"
                             : "=r"(a[mi][0]), "=r"(a[mi][1]), "=r"(a[mi][2]), "=r"(a[mi][3])
                             : "r"(addr));
            }
            #pragma unroll
            for (int p = 0; p < 2; p++) {
                int g = lane >> 3, r = lane & 7;
                int row = wn * 32 + p * 16 + (g >> 1) * 8 + r;
                unsigned addr = bs_base + (row * PITCH + ks + (g & 1) * 8) * 2;
                unsigned r0, r1, r2, r3;
                asm volatile("ldmatrix.sync.aligned.m8n8.x4.shared.b16 {%0,%1,%2,%3}, [%4];"
                             : "=r"(r0), "=r"(r1), "=r"(r2), "=r"(r3) : "r"(addr));
                b[p * 2][0] = r0;  b[p * 2][1] = r1;
                b[p * 2 + 1][0] = r2;  b[p * 2 + 1][1] = r3;
            }
            #pragma unroll
            for (int mi = 0; mi < 4; mi++)
                #pragma unroll
                for (int ni = 0; ni < 4; ni++) {
                    asm volatile(
                        "mma.sync.aligned.m16n8k16.row.col.f32.bf16.bf16.f32 "
                        "{%0,%1,%2,%3}, {%4,%5,%6,%7}, {%8,%9}, {%0,%1,%2,%3};"
                        : "+f"(acc[mi][ni][0]), "+f"(acc[mi][ni][1]),
                          "+f"(acc[mi][ni][2]), "+f"(acc[mi][ni][3])
                        : "r"(a[mi][0]), "r"(a[mi][1]), "r"(a[mi][2]), "r"(a[mi][3]),
                          "r"(b[ni][0]), "r"(b[ni][1]));
                }
        }
        __syncthreads();
    }

    if (isGram) {
        // epilogue: D -> multi-gamma RBF -> class histogram (single-counted)
        #pragma unroll
        for (int mi = 0; mi < 4; mi++) {
            int rbase = wm * 64 + mi * 16 + (lane >> 2);
            #pragma unroll
            for (int ni = 0; ni < 4; ni++) {
                int cbase = wn * 32 + ni * 8 + (lane & 3) * 2;
                #pragma unroll
                for (int rr = 0; rr < 2; rr++) {
                    int il = rbase + rr * 8;
                    int aCls = ci_s[il];
                    if (aCls < 0) continue;
                    float si = sqi[il];
                    #pragma unroll
                    for (int cc = 0; cc < 2; cc++) {
                        int jl = cbase + cc;
                        int bCls = cj_s[jl];
                        if (bCls < 0) continue;
                        if (diag) {
                            if (jl < il) continue;
                            if (jl == il) { atomicAdd(&bins[wid * 256 + aCls * 17], 2.5f); continue; }
                        }
                        float dot = acc[mi][ni][rr * 2 + cc];
                        float D = si + sqj[jl] - 2.f * dot;
                        float Kv = __expf(-0.01f * D);
                        if (D < 340.f) {
                            Kv += __expf(-0.1f * D) + __expf(-D)
                                + __expf(-10.f * D) + __expf(-100.f * D);
                        }
                        atomicAdd(&bins[wid * 256 + aCls * 16 + bCls], Kv);
                    }
                }
            }
        }
        __syncthreads();
        {
            float s = 0.f;
            #pragma unroll
            for (int w = 0; w < 8; w++) s += bins[w * 256 + tid];
            atomicAdd(&g_G[set][tid], s);
        }
    } else {
        float* out = g_M[pair];
        #pragma unroll
        for (int mi = 0; mi < 4; mi++)
            #pragma unroll
            for (int ni = 0; ni < 4; ni++)
                #pragma unroll
                for (int rr = 0; rr < 2; rr++) {
                    int row = tp + wm * 64 + mi * 16 + (lane >> 2) + rr * 8;
                    int col = tq + wn * 32 + ni * 8 + (lane & 3) * 2;
                    atomicAdd(&out[row * 256 + col], acc[mi][ni][rr * 2]);
                    atomicAdd(&out[row * 256 + col + 1], acc[mi][ni][rr * 2 + 1]);
                }
    }
}

// =======================================================================
// Kernel E: hsic reduce (512 blocks, 1 elem/thread over 512KB)
//           + last-block PARALLEL combine
// =======================================================================
__global__ void reduce_combine_kernel(float* __restrict__ out) {
    int tid = threadIdx.x;
    int bx = blockIdx.x;
    const float invB = 1.f / (float)BN;
    __shared__ float red[256];

    int g = bx * 256 + tid;              // 131072 threads total
    int pair = g >> 16;
    int e = g & 65535;
    int p = e >> 8, q = e & 255;
    float s0 = g_M[pair][e];
    float cp = (pair == 0) ? g_colsum[0][p] : g_colsum[2][p];
    float cq = (pair == 0) ? g_colsum[1][q] : g_colsum[3][q];
    float m0 = s0 - cp * cq * invB;
    red[tid] = m0 * m0;
    __syncthreads();
    for (int s = 128; s; s >>= 1) { if (tid < s) red[tid] += red[tid + s]; __syncthreads(); }
    if (tid == 0) g_hpart[bx] = red[0];
    __threadfence();

    __shared__ int is_last;
    if (tid == 0) {
        int t = atomicAdd(&g_ticket, 1);
        is_last = (t == 511) ? 1 : 0;
    }
    __syncthreads();
    if (!is_last) return;
    if (tid == 0) g_ticket = 0;     // self-reset for next replay

    // ---- last block: cooperative staging into smem, then parallel combine ----
    __shared__ float sh_G[512];      // both 16x16 histograms
    __shared__ float sh_ls[5];       // small-loss sums
    __shared__ float cntS[16];
    __shared__ float sh_mmd[2];
    __shared__ float sh_cnt2[2];

    sh_G[tid] = ((const float*)g_G)[tid];
    sh_G[tid + 256] = ((const float*)g_G)[tid + 256];
    if (tid < 16) cntS[tid] = 0.f;
    if (tid < 5) sh_ls[tid] = 0.f;
    if (tid < 2) { sh_mmd[tid] = 0.f; sh_cnt2[tid] = 0.f; }
    __syncthreads();

    for (int r = tid; r < BN; r += 256) {
        int c = g_cls[r];
        if (c >= 0) atomicAdd(&cntS[c], 1.f);
    }
    if (tid < 80) atomicAdd(&sh_ls[tid >> 4], g_lpart[tid >> 4][tid & 15]);

    float hp = g_hpart[tid] + g_hpart[tid + 256];
    float rp = g_rpart[tid] + g_rpart[tid + 256];
    __syncthreads();   // cntS, sh_G ready before mmd terms

    if (tid < 48) {
        int s = tid / 24, r2 = tid % 24;
        int lab = r2 / 6, pr = r2 % 6;
        int d1 = (pr < 3) ? 0 : (pr < 5) ? 1 : 2;
        int d2 = (pr < 3) ? pr + 1 : (pr < 5) ? pr - 1 : 3;
        int a = lab * 4 + d1, b = lab * 4 + d2;
        float n1 = cntS[a], n2 = cntS[b];
        if (n1 > 1.f && n2 > 1.f) {
            const float* G = sh_G + s * 256;
            float ga = 2.f * G[a * 16 + a];
            float gb = 2.f * G[b * 16 + b];
            float gab = G[a * 16 + b] + G[b * 16 + a];
            float m1m = fmaxf(n1, 1.f), m2m = fmaxf(n2, 1.f);
            float term = ga / (m1m * m1m) + gb / (m2m * m2m)
                       - 2.f * gab / fmaxf(n1 * n2, 1.f);
            atomicAdd(&sh_mmd[s], term);
            atomicAdd(&sh_cnt2[s], 1.f);
        }
    }

    red[tid] = hp;
    __syncthreads();
    for (int s = 128; s; s >>= 1) { if (tid < s) red[tid] += red[tid + s]; __syncthreads(); }
    float hsic_frob = red[0];
    __syncthreads();
    red[tid] = rp;
    __syncthreads();
    for (int s = 128; s; s >>= 1) { if (tid < s) red[tid] += red[tid + s]; __syncthreads(); }
    float recon_sum = red[0];
    __syncthreads();

    if (tid == 0) {
        float hsic_sum = hsic_frob / (4095.f * 4095.f);
        float mmd0 = sh_mmd[0] / fmaxf(sh_cnt2[0], 1.f);
        float mmd1 = sh_mmd[1] / fmaxf(sh_cnt2[1], 1.f);
        float msum = 0.f;
        #pragma unroll
        for (int k = 0; k < 16; k++) msum += cntS[k];
        msum = fmaxf(msum, 1.f);

        float total = 0.4f * sh_ls[0] / msum + 0.3f * sh_ls[1] / msum + 0.3f * sh_ls[2] / msum;
        total += 0.1f * (sh_ls[3] / msum + sh_ls[4] / msum + mmd0 + mmd1);
        total += 0.1f * hsic_sum;
        total += recon_sum / (float)(BN * HN);
        out[0] = total;
    }
}

// ---------------- launch ----------------
extern "C" void kernel_launch(void* const* d_in, const int* in_sizes, int n_in,
                              void* d_out, int out_size) {
    (void)in_sizes; (void)n_in; (void)out_size;
    const float* logits1 = (const float*)d_in[0];
    const int*   labels1 = (const int*)d_in[1];
    const float* logits2 = (const float*)d_in[2];
    const int*   labels2 = (const int*)d_in[3];
    const float* logits3 = (const float*)d_in[4];
    const int*   labels3 = (const int*)d_in[5];
    const float* c_v  = (const float*)d_in[6];
    const float* s_v  = (const float*)d_in[7];
    const float* c_t  = (const float*)d_in[8];
    const float* s_t  = (const float*)d_in[9];
    const float* v_sv = (const float*)d_in[10];
    const float* v_st = (const float*)d_in[11];
    const int*   dom  = (const int*)d_in[12];
    const unsigned char* mask = (const unsigned char*)d_in[13];
    const float* hir = (const float*)d_in[14];
    const float* hio = (const float*)d_in[15];
    const float* htr = (const float*)d_in[16];
    const float* hto = (const float*)d_in[17];

    cudaFuncSetAttribute(gram_hsic_kernel,
                         cudaFuncAttributeMaxDynamicSharedMemorySize, SMEM_CD);

    prep_kernel<<<dim3(512, 6), 256>>>(c_v, c_t, s_v, s_t, labels1, dom, mask,
                                       logits1, labels1, logits2, labels2, logits3, labels3,
                                       v_sv, v_st, hir, hio, htr, hto);
    transposeN_kernel<<<dim3(64, 4, 4), 256>>>(c_v, s_v, c_t, s_t);
    gram_hsic_kernel<<<1184, 256, SMEM_CD>>>();
    reduce_combine_kernel<<<512, 256>>>((float*)d_out);
}